// round 2
// baseline (speedup 1.0000x reference)
#include <cuda_runtime.h>
#include <math.h>

#define Bn 8
#define HW 4096
#define Mm 32768   // B*HW
#define HD 64

// Scratch (static device globals; no allocation allowed)
__device__ float g_qkv[9u * Mm * HD];      // [s*3+i][m][c], s=q/k/v, i=dil branch
__device__ float g_off[2][Mm * 18];        // offsets for dil 2,3
__device__ float g_defk[2][Mm * HD];       // deformed k for dil 2,3
__device__ float g_defv[2][Mm * HD];       // deformed v for dil 2,3
__device__ float g_attn[Mm * 192];         // concatenated attention outputs

// ---------------------------------------------------------------------------
// SGEMM: C[m,n] = sum_k A[m,k] * Bw[n,k]  (A row-major 192, Bw row-major 192)
// mode 0: scatter into g_qkv[(n/64)][m][n%64]   (qkv projection, N=576)
// mode 1: Cout[m*192+n] = acc + bias[n], A taken from g_attn (final proj)
// ---------------------------------------------------------------------------
__global__ __launch_bounds__(256) void sgemm_kernel(
    const float* __restrict__ A, const float* __restrict__ Bw,
    const float* __restrict__ bias, float* __restrict__ Cout, int mode)
{
    const int Kdim = 192;
    __shared__ float As[16][65];
    __shared__ float Bs[16][65];
    int tid = threadIdx.x;
    int tx = tid & 15, ty = tid >> 4;
    int m0 = blockIdx.x * 64, n0 = blockIdx.y * 64;
    const float* Ap = (mode == 0) ? A : g_attn;
    float acc[4][4] = {};
    for (int k0 = 0; k0 < Kdim; k0 += 16) {
        #pragma unroll
        for (int i = 0; i < 4; i++) {
            int idx = tid + i * 256;
            int mm = idx >> 4, kk = idx & 15;
            As[kk][mm] = Ap[(m0 + mm) * Kdim + k0 + kk];
        }
        #pragma unroll
        for (int i = 0; i < 4; i++) {
            int idx = tid + i * 256;
            int nn = idx >> 4, kk = idx & 15;
            Bs[kk][nn] = Bw[(n0 + nn) * Kdim + k0 + kk];
        }
        __syncthreads();
        #pragma unroll
        for (int kk = 0; kk < 16; kk++) {
            float a[4], bb[4];
            #pragma unroll
            for (int i = 0; i < 4; i++) a[i] = As[kk][ty * 4 + i];
            #pragma unroll
            for (int j = 0; j < 4; j++) bb[j] = Bs[kk][tx * 4 + j];
            #pragma unroll
            for (int i = 0; i < 4; i++)
                #pragma unroll
                for (int j = 0; j < 4; j++)
                    acc[i][j] += a[i] * bb[j];
        }
        __syncthreads();
    }
    if (mode == 0) {
        size_t bufbase = (size_t)blockIdx.y * Mm * 64;
        #pragma unroll
        for (int i = 0; i < 4; i++) {
            int m = m0 + ty * 4 + i;
            #pragma unroll
            for (int j = 0; j < 4; j++) {
                int c = tx * 4 + j;
                g_qkv[bufbase + (size_t)m * 64 + c] = acc[i][j];
            }
        }
    } else {
        #pragma unroll
        for (int i = 0; i < 4; i++) {
            int m = m0 + ty * 4 + i;
            #pragma unroll
            for (int j = 0; j < 4; j++) {
                int n = n0 + tx * 4 + j;
                Cout[(size_t)m * 192 + n] = acc[i][j] + bias[n];
            }
        }
    }
}

// ---------------------------------------------------------------------------
// Offset conv: dilated 3x3 conv on (undeformed) k branch, 64 -> 18 channels,
// padding = dil (zero padded). One thread per (pixel, out-channel).
// blockDim = (18, 16). Output layout [m][kk*2+comp].
// ---------------------------------------------------------------------------
__global__ void offconv_kernel(const float* __restrict__ ow,
                               const float* __restrict__ ob, int dil_idx)
{
    int dil = dil_idx + 2;
    const float* kin = &g_qkv[(size_t)(4 + dil_idx) * Mm * HD];
    float* offout = g_off[dil_idx];
    int oc = threadIdx.x;  // 0..17
    int m = blockIdx.x * 16 + threadIdx.y;
    int b = m >> 12, hw = m & 4095, h = hw >> 6, w = hw & 63;
    float acc = ob[oc];
    for (int kk = 0; kk < 9; kk++) {
        int y = h + (kk / 3 - 1) * dil;
        int x = w + (kk % 3 - 1) * dil;
        if ((unsigned)y < 64u && (unsigned)x < 64u) {
            const float* kp = kin + (size_t)((b << 12) + (y << 6) + x) * 64;
            const float* wp = ow + oc * 576 + kk;
            #pragma unroll
            for (int c = 0; c < 64; c++) acc += kp[c] * wp[c * 9];
        }
    }
    offout[m * 18 + oc] = acc;
}

// ---------------------------------------------------------------------------
// Deformable conv for k AND v (shared offsets + shared weights def_w/def_b).
// Block = 256 threads, 8 pixels. For each of 8 c-chunks (8 channels x 9 taps
// = 72 idx): cooperatively stage weight chunk + bilinear-sample both tensors
// into smem, then accumulate the 64-output GEMM per pixel.
// ---------------------------------------------------------------------------
#define DPX 8
__global__ __launch_bounds__(256) void deform_kernel(
    const float* __restrict__ dw, const float* __restrict__ db, int dil_idx)
{
    __shared__ float s_k[DPX * 72];
    __shared__ float s_v[DPX * 72];
    __shared__ float w_s[64 * 73];
    __shared__ int   s_base[4][DPX * 9];
    __shared__ float s_wgt[4][DPX * 9];

    int dil = dil_idx + 2;
    const float* kin = &g_qkv[(size_t)(4 + dil_idx) * Mm * HD];
    const float* vin = &g_qkv[(size_t)(7 + dil_idx) * Mm * HD];
    const float* off = g_off[dil_idx];
    float* kout = g_defk[dil_idx];
    float* vout = g_defv[dil_idx];

    int tid = threadIdx.x;
    int m0 = blockIdx.x * DPX;
    int bb = m0 >> 12;   // whole block shares batch index (4096 % 8 == 0)

    if (tid < DPX * 9) {
        int px = tid / 9, kk = tid % 9;
        int m = m0 + px;
        int hw = m & 4095;
        int h = hw >> 6, w = hw & 63;
        float oy = off[m * 18 + kk * 2 + 0];
        float ox = off[m * 18 + kk * 2 + 1];
        float py  = (float)(h + (kk / 3 - 1) * dil) + oy;
        float pxf = (float)(w + (kk % 3 - 1) * dil) + ox;
        float y0f = floorf(py), x0f = floorf(pxf);
        float wy = py - y0f, wx = pxf - x0f;
        int y0 = (int)y0f, x0 = (int)x0f;
        int   ys[2]  = {y0, y0 + 1};
        int   xs[2]  = {x0, x0 + 1};
        float wys[2] = {1.f - wy, wy};
        float wxs[2] = {1.f - wx, wx};
        #pragma unroll
        for (int cy = 0; cy < 2; cy++)
            #pragma unroll
            for (int cx = 0; cx < 2; cx++) {
                int ci = cy * 2 + cx;
                int y = ys[cy], x = xs[cx];
                bool valid = ((unsigned)y < 64u) && ((unsigned)x < 64u);
                s_base[ci][tid] = valid ? ((y << 6) + x) : -1;
                s_wgt[ci][tid]  = wys[cy] * wxs[cx];
            }
    }
    __syncthreads();

    int px_g = tid >> 5;       // warp -> pixel
    int o_g  = tid & 31;       // lane -> out channel (and +32)
    float acck0 = db[o_g], acck1 = db[o_g + 32];
    float accv0 = acck0,  accv1 = acck1;

    for (int ch = 0; ch < 8; ch++) {
        // stage weight chunk: w_s[o][di] = dw[o*576 + ch*72 + di]
        for (int i = tid; i < 64 * 72; i += 256) {
            int o = i / 72, di = i % 72;
            w_s[o * 73 + di] = dw[o * 576 + ch * 72 + di];
        }
        // bilinear-sample this 8-channel chunk for both tensors
        for (int it = tid; it < DPX * 72; it += 256) {
            int px = it / 72;
            int r  = it % 72;
            int kk = r / 8, lc = r % 8;
            int pk = px * 9 + kk;
            int c  = ch * 8 + lc;
            float vk = 0.f, vv = 0.f;
            #pragma unroll
            for (int ci = 0; ci < 4; ci++) {
                int base = s_base[ci][pk];
                if (base >= 0) {
                    float wgt = s_wgt[ci][pk];
                    int idx = ((bb << 12) + base) * 64 + c;
                    vk += kin[idx] * wgt;
                    vv += vin[idx] * wgt;
                }
            }
            int di = lc * 9 + kk;   // matches weight chunk ordering
            s_k[px * 72 + di] = vk;
            s_v[px * 72 + di] = vv;
        }
        __syncthreads();
        #pragma unroll 8
        for (int di = 0; di < 72; di++) {
            float sk = s_k[px_g * 72 + di];
            float sv = s_v[px_g * 72 + di];
            float w0 = w_s[o_g * 73 + di];
            float w1 = w_s[(o_g + 32) * 73 + di];
            acck0 += sk * w0; acck1 += sk * w1;
            accv0 += sv * w0; accv1 += sv * w1;
        }
        __syncthreads();
    }
    int m = m0 + px_g;
    kout[(size_t)m * 64 + o_g]      = acck0;
    kout[(size_t)m * 64 + o_g + 32] = acck1;
    vout[(size_t)m * 64 + o_g]      = accv0;
    vout[(size_t)m * 64 + o_g + 32] = accv1;
}

// ---------------------------------------------------------------------------
// Attention: warp per pixel, grid (4096, 3 dilations). 9-tap softmax.
// Out-of-bounds taps contribute logit EXACTLY 0 (zero-padded k) and v=0,
// matching unfold3's zero padding inside the softmax.
// ---------------------------------------------------------------------------
__global__ __launch_bounds__(256) void attn_kernel()
{
    int dil_idx = blockIdx.y;
    int dil = dil_idx + 1;
    int warp = threadIdx.x >> 5, lane = threadIdx.x & 31;
    int m = blockIdx.x * 8 + warp;
    int b = m >> 12, hw = m & 4095, h = hw >> 6, w = hw & 63;
    const float* q = &g_qkv[(size_t)dil_idx * Mm * HD];
    const float *kb, *vb;
    if (dil_idx == 0) {
        kb = &g_qkv[(size_t)3 * Mm * HD];
        vb = &g_qkv[(size_t)6 * Mm * HD];
    } else {
        kb = g_defk[dil_idx - 1];
        vb = g_defv[dil_idx - 1];
    }
    float q0 = q[(size_t)m * 64 + lane];
    float q1 = q[(size_t)m * 64 + 32 + lane];
    float eg[9];
    int nb[9];
    float mx = -1e30f;
    #pragma unroll
    for (int j = 0; j < 9; j++) {
        int y = h + (j / 3 - 1) * dil;
        int x = w + (j % 3 - 1) * dil;
        bool valid = ((unsigned)y < 64u) && ((unsigned)x < 64u);
        float p = 0.f;
        int base = -1;
        if (valid) {
            base = (b << 12) + (y << 6) + x;
            p = q0 * kb[(size_t)base * 64 + lane] + q1 * kb[(size_t)base * 64 + 32 + lane];
        }
        nb[j] = base;
        #pragma unroll
        for (int s = 16; s; s >>= 1) p += __shfl_xor_sync(0xffffffffu, p, s);
        eg[j] = p * 0.125f;   // scale = 64^-0.5; exactly 0 for padded taps
        mx = fmaxf(mx, eg[j]);
    }
    float sum = 0.f;
    #pragma unroll
    for (int j = 0; j < 9; j++) { eg[j] = expf(eg[j] - mx); sum += eg[j]; }
    float inv = 1.f / sum;
    float o0 = 0.f, o1 = 0.f;
    #pragma unroll
    for (int j = 0; j < 9; j++) {
        if (nb[j] >= 0) {
            float a = eg[j] * inv;
            o0 += a * vb[(size_t)nb[j] * 64 + lane];
            o1 += a * vb[(size_t)nb[j] * 64 + 32 + lane];
        }
    }
    g_attn[(size_t)m * 192 + dil_idx * 64 + lane]      = o0;
    g_attn[(size_t)m * 192 + dil_idx * 64 + 32 + lane] = o1;
}

// ---------------------------------------------------------------------------
extern "C" void kernel_launch(void* const* d_in, const int* in_sizes, int n_in,
                              void* d_out, int out_size)
{
    const float* x      = (const float*)d_in[0];
    const float* qkv_w  = (const float*)d_in[1];
    const float* proj_w = (const float*)d_in[2];
    const float* proj_b = (const float*)d_in[3];
    const float* off_w2 = (const float*)d_in[4];
    const float* off_b2 = (const float*)d_in[5];
    const float* def_w2 = (const float*)d_in[6];
    const float* def_b2 = (const float*)d_in[7];
    const float* off_w3 = (const float*)d_in[8];
    const float* off_b3 = (const float*)d_in[9];
    const float* def_w3 = (const float*)d_in[10];
    const float* def_b3 = (const float*)d_in[11];
    float* out = (float*)d_out;

    // 1) qkv projection: (32768 x 192) @ (192 x 576) -> scattered per-branch
    sgemm_kernel<<<dim3(512, 9), 256>>>(x, qkv_w, nullptr, nullptr, 0);

    // 2) offset convs (dil 2, 3)
    dim3 offblk(18, 16);
    offconv_kernel<<<2048, offblk>>>(off_w2, off_b2, 0);
    offconv_kernel<<<2048, offblk>>>(off_w3, off_b3, 1);

    // 3) deformable conv on k and v (dil 2, 3)
    deform_kernel<<<4096, 256>>>(def_w2, def_b2, 0);
    deform_kernel<<<4096, 256>>>(def_w3, def_b3, 1);

    // 4) local attention, all 3 dilations
    attn_kernel<<<dim3(4096, 3), 256>>>();

    // 5) output projection + bias -> d_out
    sgemm_kernel<<<dim3(512, 3), 256>>>(nullptr, proj_w, proj_b, out, 1);
}

// round 5
// speedup vs baseline: 2.2060x; 2.2060x over previous
#include <cuda_runtime.h>
#include <math.h>

#define Bn 8
#define HW 4096
#define Mm 32768   // B*HW
#define HD 64

// Scratch (static device globals; no allocation allowed)
__device__ __align__(16) float g_qkv[9u * Mm * HD];   // [s*3+i][m][c]
__device__ __align__(16) float g_off[2][Mm * 18];     // offsets for dil 2,3
__device__ __align__(16) float g_defk[2][Mm * HD];    // deformed k
__device__ __align__(16) float g_defv[2][Mm * HD];    // deformed v
__device__ __align__(16) float g_attn[Mm * 192];      // attention outputs

// ---------------------------------------------------------------------------
// SGEMM: C[m,n] = sum_k A[m,k] * Bw[n,k]; 128x64 tile, 8x4 micro, k-chunk 16.
// mode 0: scatter into g_qkv[(n/64)][m][n%64]   (qkv projection, N=576)
// mode 1: Cout[m*192+n] = acc + bias[n], A taken from g_attn (final proj)
// ---------------------------------------------------------------------------
__global__ __launch_bounds__(256) void sgemm_kernel(
    const float* __restrict__ A, const float* __restrict__ Bw,
    const float* __restrict__ bias, float* __restrict__ Cout, int mode)
{
    __shared__ __align__(16) float As[16][132];
    __shared__ __align__(16) float Bs[16][68];
    int tid = threadIdx.x;
    int tx = tid & 15, ty = tid >> 4;    // tx: 4 n's, ty: 8 m's
    int m0 = blockIdx.x * 128, n0 = blockIdx.y * 64;
    const float* Ap = (mode == 0) ? A : g_attn;
    float acc[8][4] = {};

    for (int k0 = 0; k0 < 192; k0 += 16) {
        // stage A tile: 128 x 16 (512 float4 slots, 2 per thread)
        #pragma unroll
        for (int s = 0; s < 2; s++) {
            int u = tid + s * 256;
            int mm = u >> 2, kq = u & 3;
            float4 av = *(const float4*)&Ap[(size_t)(m0 + mm) * 192 + k0 + kq * 4];
            As[kq * 4 + 0][mm] = av.x;
            As[kq * 4 + 1][mm] = av.y;
            As[kq * 4 + 2][mm] = av.z;
            As[kq * 4 + 3][mm] = av.w;
        }
        // stage B tile: 64 x 16 (256 float4 slots, 1 per thread)
        {
            int nn = tid >> 2, kq = tid & 3;
            float4 bv = *(const float4*)&Bw[(size_t)(n0 + nn) * 192 + k0 + kq * 4];
            Bs[kq * 4 + 0][nn] = bv.x;
            Bs[kq * 4 + 1][nn] = bv.y;
            Bs[kq * 4 + 2][nn] = bv.z;
            Bs[kq * 4 + 3][nn] = bv.w;
        }
        __syncthreads();
        #pragma unroll
        for (int kk = 0; kk < 16; kk++) {
            float4 a0 = *(const float4*)&As[kk][ty * 8];
            float4 a1 = *(const float4*)&As[kk][ty * 8 + 4];
            float4 b  = *(const float4*)&Bs[kk][tx * 4];
            float a[8] = {a0.x, a0.y, a0.z, a0.w, a1.x, a1.y, a1.z, a1.w};
            float bb[4] = {b.x, b.y, b.z, b.w};
            #pragma unroll
            for (int i = 0; i < 8; i++)
                #pragma unroll
                for (int j = 0; j < 4; j++)
                    acc[i][j] += a[i] * bb[j];
        }
        __syncthreads();
    }

    if (mode == 0) {
        size_t bufbase = (size_t)blockIdx.y * Mm * 64;
        #pragma unroll
        for (int i = 0; i < 8; i++) {
            int m = m0 + ty * 8 + i;
            float4 v = {acc[i][0], acc[i][1], acc[i][2], acc[i][3]};
            *(float4*)&g_qkv[bufbase + (size_t)m * 64 + tx * 4] = v;
        }
    } else {
        float4 b4 = *(const float4*)&bias[n0 + tx * 4];
        #pragma unroll
        for (int i = 0; i < 8; i++) {
            int m = m0 + ty * 8 + i;
            float4 v = {acc[i][0] + b4.x, acc[i][1] + b4.y,
                        acc[i][2] + b4.z, acc[i][3] + b4.w};
            *(float4*)&Cout[(size_t)m * 192 + n0 + tx * 4] = v;
        }
    }
}

// ---------------------------------------------------------------------------
// Offset conv: dilated 3x3 conv on k branch, 64 -> 18 ch, zero pad = dil.
// Block: 32 pixels (8 warps x 4 px). Lanes = (px_sub 4) x (channel-octet 8).
// Weights staged transposed in smem: ws[oc][kk][c] (c padded to 68).
// ---------------------------------------------------------------------------
__global__ __launch_bounds__(256) void offconv_kernel(
    const float* __restrict__ ow, const float* __restrict__ ob, int dil_idx)
{
    __shared__ __align__(16) float ws[18 * 612];
    int dil = dil_idx + 2;
    const float* kin = &g_qkv[(size_t)(4 + dil_idx) * Mm * HD];
    float* offout = g_off[dil_idx];
    int tid = threadIdx.x;

    for (int i = tid; i < 18 * 576; i += 256) {
        int oc = i / 576, r = i % 576, c = r / 9, kk = r % 9;
        ws[oc * 612 + kk * 68 + c] = ow[i];
    }
    __syncthreads();

    int wr = tid >> 5, lane = tid & 31;
    int pxs = lane >> 3, cq = lane & 7;
    int m = blockIdx.x * 32 + wr * 4 + pxs;
    int b = m >> 12, hw = m & 4095, h = hw >> 6, w = hw & 63;

    float acc[18];
    #pragma unroll
    for (int oc = 0; oc < 18; oc++) acc[oc] = 0.f;

    for (int kk = 0; kk < 9; kk++) {
        int y = h + (kk / 3 - 1) * dil;
        int x = w + (kk % 3 - 1) * dil;
        float4 k0 = {0.f, 0.f, 0.f, 0.f}, k1 = {0.f, 0.f, 0.f, 0.f};
        if ((unsigned)y < 64u && (unsigned)x < 64u) {
            const float* kp = kin + (size_t)((b << 12) + (y << 6) + x) * 64 + cq * 8;
            k0 = *(const float4*)kp;
            k1 = *(const float4*)(kp + 4);
        }
        const float* wsk = ws + kk * 68 + cq * 8;
        #pragma unroll
        for (int oc = 0; oc < 18; oc++) {
            float4 w0 = *(const float4*)(wsk + oc * 612);
            float4 w1 = *(const float4*)(wsk + oc * 612 + 4);
            acc[oc] += k0.x * w0.x + k0.y * w0.y + k0.z * w0.z + k0.w * w0.w
                     + k1.x * w1.x + k1.y * w1.y + k1.z * w1.z + k1.w * w1.w;
        }
    }
    // reduce over the 8 channel-octet lanes
    #pragma unroll
    for (int oc = 0; oc < 18; oc++) {
        float a = acc[oc];
        a += __shfl_xor_sync(0xffffffffu, a, 1);
        a += __shfl_xor_sync(0xffffffffu, a, 2);
        a += __shfl_xor_sync(0xffffffffu, a, 4);
        acc[oc] = a;
    }
    if (cq == 0) {
        #pragma unroll
        for (int oc = 0; oc < 18; oc++)
            offout[(size_t)m * 18 + oc] = acc[oc] + ob[oc];
    }
}

// ---------------------------------------------------------------------------
// Deformable conv for k AND v. Block: 32 px x 64 out. Register-tiled GEMM:
// thread = (tx: 4 px) x (ty: 2 out) x 2 tensors = 16 acc. K chunked 8 x 72.
// Sampling: lanes = (corner 4) x (channel 8), shfl-reduce corners.
// ---------------------------------------------------------------------------
__global__ __launch_bounds__(256) void deform_kernel(
    const float* __restrict__ dw, const float* __restrict__ db, int dil_idx)
{
    __shared__ __align__(16) float s_k[72][36];
    __shared__ __align__(16) float s_v[72][36];
    __shared__ float w_s[64 * 73];
    __shared__ int   s_base[4][32 * 9];
    __shared__ float s_wgt[4][32 * 9];

    int dil = dil_idx + 2;
    const float* kin = &g_qkv[(size_t)(4 + dil_idx) * Mm * HD];
    const float* vin = &g_qkv[(size_t)(7 + dil_idx) * Mm * HD];
    const float* off = g_off[dil_idx];
    float* kout = g_defk[dil_idx];
    float* vout = g_defv[dil_idx];

    int tid = threadIdx.x;
    int m0 = blockIdx.x * 32;
    int bpix = m0 & ~4095;   // batch pixel base (block within one batch)

    // precompute bilinear corners for 32 px x 9 taps
    for (int i = tid; i < 32 * 9; i += 256) {
        int px = i / 9, kk = i % 9;
        int m = m0 + px;
        int hw = m & 4095;
        int h = hw >> 6, w = hw & 63;
        float oy = off[(size_t)m * 18 + kk * 2 + 0];
        float ox = off[(size_t)m * 18 + kk * 2 + 1];
        float py  = (float)(h + (kk / 3 - 1) * dil) + oy;
        float pxf = (float)(w + (kk % 3 - 1) * dil) + ox;
        float y0f = floorf(py), x0f = floorf(pxf);
        float wy = py - y0f, wx = pxf - x0f;
        int y0 = (int)y0f, x0 = (int)x0f;
        int   ys[2]  = {y0, y0 + 1};
        int   xs[2]  = {x0, x0 + 1};
        float wys[2] = {1.f - wy, wy};
        float wxs[2] = {1.f - wx, wx};
        #pragma unroll
        for (int cy = 0; cy < 2; cy++)
            #pragma unroll
            for (int cx = 0; cx < 2; cx++) {
                int ci = cy * 2 + cx;
                int y = ys[cy], x = xs[cx];
                bool valid = ((unsigned)y < 64u) && ((unsigned)x < 64u);
                s_base[ci][i] = valid ? ((y << 6) + x) : -1;
                s_wgt[ci][i]  = wys[cy] * wxs[cx];
            }
    }
    __syncthreads();

    int tx = tid & 7, ty = tid >> 3;       // tx: px-quad, ty: out-pair
    int wr = tid >> 5, lane = tid & 31;
    int corner = lane >> 3, lc = lane & 7;

    float b0 = db[ty * 2], b1 = db[ty * 2 + 1];
    float ak0[4], ak1[4], av0[4], av1[4];
    #pragma unroll
    for (int j = 0; j < 4; j++) { ak0[j] = b0; ak1[j] = b1; av0[j] = b0; av1[j] = b1; }

    for (int ch = 0; ch < 8; ch++) {
        // stage weight chunk: w_s[o][di], di = lc*9+kk within chunk
        for (int i = tid; i < 64 * 72; i += 256) {
            int o = i / 72, di = i % 72;
            w_s[o * 73 + di] = dw[o * 576 + ch * 72 + di];
        }
        // sample this chunk: 8 warps x 36 (px,tap) pairs
        for (int t = 0; t < 36; t++) {
            int p = wr * 36 + t;
            int px = p / 9, kk = p % 9;
            int base = s_base[corner][p];
            float wgt = s_wgt[corner][p];
            float vk = 0.f, vv = 0.f;
            if (base >= 0) {
                int idx = (bpix + base) * 64 + ch * 8 + lc;
                vk = kin[idx] * wgt;
                vv = vin[idx] * wgt;
            }
            vk += __shfl_xor_sync(0xffffffffu, vk, 8);
            vk += __shfl_xor_sync(0xffffffffu, vk, 16);
            vv += __shfl_xor_sync(0xffffffffu, vv, 8);
            vv += __shfl_xor_sync(0xffffffffu, vv, 16);
            if (lane < 8) {
                s_k[lane * 9 + kk][px] = vk;
                s_v[lane * 9 + kk][px] = vv;
            }
        }
        __syncthreads();
        #pragma unroll 4
        for (int di = 0; di < 72; di++) {
            float4 k4 = *(const float4*)&s_k[di][tx * 4];
            float4 v4 = *(const float4*)&s_v[di][tx * 4];
            float w0 = w_s[(ty * 2) * 73 + di];
            float w1 = w_s[(ty * 2 + 1) * 73 + di];
            ak0[0] += k4.x * w0; ak1[0] += k4.x * w1;
            ak0[1] += k4.y * w0; ak1[1] += k4.y * w1;
            ak0[2] += k4.z * w0; ak1[2] += k4.z * w1;
            ak0[3] += k4.w * w0; ak1[3] += k4.w * w1;
            av0[0] += v4.x * w0; av1[0] += v4.x * w1;
            av0[1] += v4.y * w0; av1[1] += v4.y * w1;
            av0[2] += v4.z * w0; av1[2] += v4.z * w1;
            av0[3] += v4.w * w0; av1[3] += v4.w * w1;
        }
        __syncthreads();
    }
    #pragma unroll
    for (int j = 0; j < 4; j++) {
        int m = m0 + tx * 4 + j;
        float2 kv = {ak0[j], ak1[j]};
        float2 vv = {av0[j], av1[j]};
        *(float2*)&kout[(size_t)m * 64 + ty * 2] = kv;
        *(float2*)&vout[(size_t)m * 64 + ty * 2] = vv;
    }
}

// ---------------------------------------------------------------------------
// Attention: warp per pixel, grid (4096, 3 dilations). 9-tap softmax.
// OOB taps contribute logit EXACTLY 0 (zero-padded unfold) and v = 0.
// ---------------------------------------------------------------------------
__global__ __launch_bounds__(256) void attn_kernel()
{
    int dil_idx = blockIdx.y;
    int dil = dil_idx + 1;
    int warp = threadIdx.x >> 5, lane = threadIdx.x & 31;
    int m = blockIdx.x * 8 + warp;
    int b = m >> 12, hw = m & 4095, h = hw >> 6, w = hw & 63;
    const float* q = &g_qkv[(size_t)dil_idx * Mm * HD];
    const float *kb, *vb;
    if (dil_idx == 0) {
        kb = &g_qkv[(size_t)3 * Mm * HD];
        vb = &g_qkv[(size_t)6 * Mm * HD];
    } else {
        kb = g_defk[dil_idx - 1];
        vb = g_defv[dil_idx - 1];
    }
    float q0 = q[(size_t)m * 64 + lane];
    float q1 = q[(size_t)m * 64 + 32 + lane];
    float eg[9];
    int nb[9];
    float mx = -1e30f;
    #pragma unroll
    for (int j = 0; j < 9; j++) {
        int y = h + (j / 3 - 1) * dil;
        int x = w + (j % 3 - 1) * dil;
        bool valid = ((unsigned)y < 64u) && ((unsigned)x < 64u);
        float p = 0.f;
        int base = -1;
        if (valid) {
            base = (b << 12) + (y << 6) + x;
            p = q0 * kb[(size_t)base * 64 + lane] + q1 * kb[(size_t)base * 64 + 32 + lane];
        }
        nb[j] = base;
        #pragma unroll
        for (int s = 16; s; s >>= 1) p += __shfl_xor_sync(0xffffffffu, p, s);
        eg[j] = p * 0.125f;
        mx = fmaxf(mx, eg[j]);
    }
    float sum = 0.f;
    #pragma unroll
    for (int j = 0; j < 9; j++) { eg[j] = expf(eg[j] - mx); sum += eg[j]; }
    float inv = 1.f / sum;
    float o0 = 0.f, o1 = 0.f;
    #pragma unroll
    for (int j = 0; j < 9; j++) {
        if (nb[j] >= 0) {
            float a = eg[j] * inv;
            o0 += a * vb[(size_t)nb[j] * 64 + lane];
            o1 += a * vb[(size_t)nb[j] * 64 + 32 + lane];
        }
    }
    g_attn[(size_t)m * 192 + dil_idx * 64 + lane]      = o0;
    g_attn[(size_t)m * 192 + dil_idx * 64 + 32 + lane] = o1;
}

// ---------------------------------------------------------------------------
extern "C" void kernel_launch(void* const* d_in, const int* in_sizes, int n_in,
                              void* d_out, int out_size)
{
    const float* x      = (const float*)d_in[0];
    const float* qkv_w  = (const float*)d_in[1];
    const float* proj_w = (const float*)d_in[2];
    const float* proj_b = (const float*)d_in[3];
    const float* off_w2 = (const float*)d_in[4];
    const float* off_b2 = (const float*)d_in[5];
    const float* def_w2 = (const float*)d_in[6];
    const float* def_b2 = (const float*)d_in[7];
    const float* off_w3 = (const float*)d_in[8];
    const float* off_b3 = (const float*)d_in[9];
    const float* def_w3 = (const float*)d_in[10];
    const float* def_b3 = (const float*)d_in[11];
    float* out = (float*)d_out;

    // 1) qkv projection: (32768 x 192) @ (192 x 576) -> per-branch buffers
    sgemm_kernel<<<dim3(256, 9), 256>>>(x, qkv_w, nullptr, nullptr, 0);

    // 2) offset convs (dil 2, 3)
    offconv_kernel<<<1024, 256>>>(off_w2, off_b2, 0);
    offconv_kernel<<<1024, 256>>>(off_w3, off_b3, 1);

    // 3) deformable conv on k and v (dil 2, 3)
    deform_kernel<<<1024, 256>>>(def_w2, def_b2, 0);
    deform_kernel<<<1024, 256>>>(def_w3, def_b3, 1);

    // 4) local attention, all 3 dilations
    attn_kernel<<<dim3(4096, 3), 256>>>();

    // 5) output projection + bias -> d_out
    sgemm_kernel<<<dim3(256, 3), 256>>>(nullptr, proj_w, proj_b, out, 1);
}